// round 3
// baseline (speedup 1.0000x reference)
#include <cuda_runtime.h>
#include <math.h>

// Problem dims
#define BB 1024
#define DD 128
#define WWID 512
#define TT 8
#define NELEM (BB*DD)      // 131072
#define HELEM (BB*WWID)    // 524288
#define MAX_STEPS 48

#define NBLK 128
#define NTHR 256
#define BM 64
#define BN 64
#define BKK 16

// Solver constants
#define RTOLc 1e-3f
#define ATOLc 1e-6f

// Tsit5 tableau
#define A21f 0.161f
#define A31f (-0.008480655492356989f)
#define A32f 0.335480655492357f
#define A41f 2.8971530571054935f
#define A42f (-6.359448489975075f)
#define A43f 4.3622954328695815f
#define A51f 5.325864828439257f
#define A52f (-11.748883564062828f)
#define A53f 7.4955393428898365f
#define A54f (-0.09249506636175525f)
#define A61f 5.86145544294642f
#define A62f (-12.92096931784711f)
#define A63f 8.159367898576159f
#define A64f (-0.071584973281401f)
#define A65f (-0.028269050394068383f)
#define Bc1 0.09646076681806523f
#define Bc2 0.01f
#define Bc3 0.4798896504144996f
#define Bc4 1.379008574103742f
#define Bc5 (-3.290069515436081f)
#define Bc6 2.324710524099774f
#define Ec1 (-0.00178001105222577714f)
#define Ec2 (-0.0008164344596567469f)
#define Ec3 0.007880878010261995f
#define Ec4 (-0.1447110071732629f)
#define Ec5 0.5823571654525552f
#define Ec6 (-0.45808210592918697f)
#define Ec7 0.015151515151515152f

// ---------------- device state ----------------
__device__ __align__(16) float g_y[NELEM];
__device__ __align__(16) float g_ynew[NELEM];
__device__ __align__(16) float g_k[7][NELEM];
__device__ __align__(16) float g_H1[HELEM];
__device__ __align__(16) float g_H2[HELEM];
__device__ __align__(16) float g_part[4][NELEM];
__device__ double g_errpart[NBLK];
__device__ volatile float g_t, g_dt, g_h, g_tns;
__device__ volatile int g_si, g_sic, g_done, g_accept, g_hit, g_wrow;
__device__ unsigned g_arrive;

__constant__ float c_coef[5][5] = {
  {A21f, 0.f,   0.f,   0.f,   0.f},
  {A31f, A32f,  0.f,   0.f,   0.f},
  {A41f, A42f,  A43f,  0.f,   0.f},
  {A51f, A52f,  A53f,  A54f,  0.f},
  {A61f, A62f,  A63f,  A64f,  A65f},
};

// -------- grid-wide barrier (all NBLK CTAs co-resident) --------
__device__ __forceinline__ void gsync() {
  __syncthreads();
  if (threadIdx.x == 0) {
    __threadfence();
    unsigned t = atomicAdd(&g_arrive, 1u) + 1u;
    unsigned target = ((t + NBLK - 1u) / NBLK) * NBLK;
    while (*(volatile unsigned*)&g_arrive < target) {}
    __threadfence();
  }
  __syncthreads();
}

__device__ __forceinline__ float softplus_f(float x) {
  return fmaxf(x, 0.f) + log1pf(expf(-fabsf(x)));
}

// A-source loader. ASRC: 0 -> y, 1..5 -> y + h*sum(a_ij k_j), 6 -> y_new, 7 -> H1, 8 -> H2
template<int ASRC>
__device__ __forceinline__ float4 load_a4(int g, float h) {
  if constexpr (ASRC == 7)      return __ldcg(reinterpret_cast<const float4*>(g_H1 + g));
  else if constexpr (ASRC == 8) return __ldcg(reinterpret_cast<const float4*>(g_H2 + g));
  else if constexpr (ASRC == 0) return __ldcg(reinterpret_cast<const float4*>(g_y + g));
  else if constexpr (ASRC == 6) return __ldcg(reinterpret_cast<const float4*>(g_ynew + g));
  else {
    float4 y4 = __ldcg(reinterpret_cast<const float4*>(g_y + g));
    float sx = 0.f, sy = 0.f, sz = 0.f, sw = 0.f;
    #pragma unroll
    for (int j = 0; j < ASRC; ++j) {
      float c = c_coef[ASRC - 1][j];
      float4 k4 = __ldcg(reinterpret_cast<const float4*>(g_k[j] + g));
      sx = fmaf(c, k4.x, sx); sy = fmaf(c, k4.y, sy);
      sz = fmaf(c, k4.z, sz); sw = fmaf(c, k4.w, sw);
    }
    float4 r;
    r.x = fmaf(h, sx, y4.x); r.y = fmaf(h, sy, y4.y);
    r.z = fmaf(h, sz, y4.z); r.w = fmaf(h, sw, y4.w);
    return r;
  }
}

// ---------- one 64x64 tile of C = act(A[M,K] @ Bw[N,K]^T + bias) ----------
template<int ASRC, int LDA, int NN, int KLEN, bool SP, bool BIAS>
__device__ __forceinline__ void gemm_tile(
    int bm, int bn, int kbase,
    const float* __restrict__ Bw, const float* __restrict__ bias, float h,
    float* __restrict__ C,
    float As[BKK][BM + 4], float Bs[BKK][BN + 4])
{
  const int tid = threadIdx.x;
  const int tx = tid & 15;
  const int ty = tid >> 4;
  const int lrow = tid >> 2;
  const int lkg  = (tid & 3) << 2;

  float acc[4][4] = {};

  // prefetch first tile
  float4 ra = load_a4<ASRC>((bm + lrow) * LDA + kbase + lkg, h);
  float4 rb = __ldg(reinterpret_cast<const float4*>(Bw + (bn + lrow) * LDA + kbase + lkg));

  for (int k0 = 0; k0 < KLEN; k0 += BKK) {
    As[lkg + 0][lrow] = ra.x; As[lkg + 1][lrow] = ra.y;
    As[lkg + 2][lrow] = ra.z; As[lkg + 3][lrow] = ra.w;
    Bs[lkg + 0][lrow] = rb.x; Bs[lkg + 1][lrow] = rb.y;
    Bs[lkg + 2][lrow] = rb.z; Bs[lkg + 3][lrow] = rb.w;
    __syncthreads();
    if (k0 + BKK < KLEN) {
      int gk = kbase + k0 + BKK + lkg;
      ra = load_a4<ASRC>((bm + lrow) * LDA + gk, h);
      rb = __ldg(reinterpret_cast<const float4*>(Bw + (bn + lrow) * LDA + gk));
    }
    #pragma unroll
    for (int kk = 0; kk < BKK; ++kk) {
      float4 a4 = *reinterpret_cast<const float4*>(&As[kk][ty << 2]);
      float4 b4 = *reinterpret_cast<const float4*>(&Bs[kk][tx << 2]);
      float av[4] = {a4.x, a4.y, a4.z, a4.w};
      float bv[4] = {b4.x, b4.y, b4.z, b4.w};
      #pragma unroll
      for (int i = 0; i < 4; ++i)
        #pragma unroll
        for (int j = 0; j < 4; ++j)
          acc[i][j] = fmaf(av[i], bv[j], acc[i][j]);
    }
    __syncthreads();
  }

  #pragma unroll
  for (int i = 0; i < 4; ++i) {
    int m = bm + (ty << 2) + i;
    float4 v; float* vp = &v.x;
    #pragma unroll
    for (int j = 0; j < 4; ++j) {
      float x = acc[i][j];
      if constexpr (BIAS) x += __ldg(bias + bn + (tx << 2) + j);
      if constexpr (SP) x = softplus_f(x);
      vp[j] = x;
    }
    __stcg(reinterpret_cast<float4*>(&C[m * NN + bn + (tx << 2)]), v);
  }
}

// ---------- split-K reduce + fused epilogues ----------
template<int STAGE>
__device__ __forceinline__ void reduce_phase(int bid, int tid,
                                             const float* __restrict__ b2,
                                             double* sd)
{
  const int idx = (bid * NTHR + tid) * 4;
  float4 p0 = __ldcg(reinterpret_cast<const float4*>(g_part[0] + idx));
  float4 p1 = __ldcg(reinterpret_cast<const float4*>(g_part[1] + idx));
  float4 p2 = __ldcg(reinterpret_cast<const float4*>(g_part[2] + idx));
  float4 p3 = __ldcg(reinterpret_cast<const float4*>(g_part[3] + idx));
  float4 bb = *reinterpret_cast<const float4*>(b2 + (idx & (DD - 1)));
  float4 v;
  v.x = p0.x + p1.x + p2.x + p3.x + bb.x;
  v.y = p0.y + p1.y + p2.y + p3.y + bb.y;
  v.z = p0.z + p1.z + p2.z + p3.z + bb.z;
  v.w = p0.w + p1.w + p2.w + p3.w + bb.w;
  __stcg(reinterpret_cast<float4*>(g_k[STAGE] + idx), v);

  if constexpr (STAGE == 5) {
    float h = g_h;
    float4 k0 = __ldcg(reinterpret_cast<const float4*>(g_k[0] + idx));
    float4 k1 = __ldcg(reinterpret_cast<const float4*>(g_k[1] + idx));
    float4 k2 = __ldcg(reinterpret_cast<const float4*>(g_k[2] + idx));
    float4 k3 = __ldcg(reinterpret_cast<const float4*>(g_k[3] + idx));
    float4 k4 = __ldcg(reinterpret_cast<const float4*>(g_k[4] + idx));
    float4 y4 = __ldcg(reinterpret_cast<const float4*>(g_y + idx));
    float4 yn;
    #pragma unroll
    for (int c = 0; c < 4; ++c) {
      float s = Bc1 * (&k0.x)[c];
      s = fmaf(Bc2, (&k1.x)[c], s);
      s = fmaf(Bc3, (&k2.x)[c], s);
      s = fmaf(Bc4, (&k3.x)[c], s);
      s = fmaf(Bc5, (&k4.x)[c], s);
      s = fmaf(Bc6, (&v.x)[c], s);
      (&yn.x)[c] = fmaf(h, s, (&y4.x)[c]);
    }
    __stcg(reinterpret_cast<float4*>(g_ynew + idx), yn);
  }

  if constexpr (STAGE == 6) {
    float h = g_h;
    float4 k0 = __ldcg(reinterpret_cast<const float4*>(g_k[0] + idx));
    float4 k1 = __ldcg(reinterpret_cast<const float4*>(g_k[1] + idx));
    float4 k2 = __ldcg(reinterpret_cast<const float4*>(g_k[2] + idx));
    float4 k3 = __ldcg(reinterpret_cast<const float4*>(g_k[3] + idx));
    float4 k4 = __ldcg(reinterpret_cast<const float4*>(g_k[4] + idx));
    float4 k5 = __ldcg(reinterpret_cast<const float4*>(g_k[5] + idx));
    float4 y4 = __ldcg(reinterpret_cast<const float4*>(g_y + idx));
    float4 yn = __ldcg(reinterpret_cast<const float4*>(g_ynew + idx));
    double ss = 0.0;
    #pragma unroll
    for (int c = 0; c < 4; ++c) {
      float e = Ec1 * (&k0.x)[c];
      e = fmaf(Ec2, (&k1.x)[c], e);
      e = fmaf(Ec3, (&k2.x)[c], e);
      e = fmaf(Ec4, (&k3.x)[c], e);
      e = fmaf(Ec5, (&k4.x)[c], e);
      e = fmaf(Ec6, (&k5.x)[c], e);
      e = fmaf(Ec7, (&v.x)[c], e);
      float err = h * e;
      float scale = ATOLc + RTOLc * fmaxf(fabsf((&y4.x)[c]), fabsf((&yn.x)[c]));
      float r = err / scale;
      ss += (double)r * (double)r;
    }
    sd[tid] = ss;
    __syncthreads();
    #pragma unroll
    for (int s2 = 128; s2 > 0; s2 >>= 1) {
      if (tid < s2) sd[tid] += sd[tid + s2];
      __syncthreads();
    }
    if (tid == 0) ((volatile double*)g_errpart)[bid] = sd[0];
  }
}

// ---------- one RK stage ----------
template<int S>
__device__ __forceinline__ void do_stage(
    int bid,
    const float* __restrict__ W0, const float* __restrict__ b0,
    const float* __restrict__ W1, const float* __restrict__ b1,
    const float* __restrict__ W2, const float* __restrict__ b2,
    float As[BKK][BM + 4], float Bs[BKK][BN + 4], double* sd)
{
  const float h = g_h;
  {
    int bm = (bid >> 3) << 6, bn = (bid & 7) << 6;
    gemm_tile<S, 128, 512, 128, true, true>(bm, bn, 0, W0, b0, h, g_H1, As, Bs);
  }
  gsync();
  {
    int bm = (bid >> 3) << 6, bn = (bid & 7) << 6;
    gemm_tile<7, 512, 512, 512, true, true>(bm, bn, 0, W1, b1, h, g_H2, As, Bs);
  }
  gsync();
  {
    int slice = bid & 3, tile = bid >> 2;
    int bm = (tile >> 1) << 6, bn = (tile & 1) << 6;
    gemm_tile<8, 512, 128, 128, false, false>(bm, bn, slice * 128, W2, nullptr, h,
                                              g_part[slice], As, Bs);
  }
  gsync();
  reduce_phase<S>(bid, threadIdx.x, b2, sd);
  gsync();
}

__device__ __forceinline__ void update_phase(int gid4, float* __restrict__ out) {
  if (g_accept) {
    float4 v = __ldcg(reinterpret_cast<const float4*>(g_ynew + gid4));
    __stcg(reinterpret_cast<float4*>(g_y + gid4), v);
    if (g_hit) {
      int r = g_wrow;
      *reinterpret_cast<float4*>(out + r * NELEM + gid4) = v;
    }
  }
}

// ---------- persistent solver ----------
__global__ void __launch_bounds__(NTHR, 1) solve_kernel(
    const float* __restrict__ ts,
    const float* __restrict__ W0, const float* __restrict__ b0,
    const float* __restrict__ W1, const float* __restrict__ b1,
    const float* __restrict__ W2, const float* __restrict__ b2,
    float* __restrict__ out)
{
  __shared__ float As[BKK][BM + 4];
  __shared__ float Bs[BKK][BN + 4];
  __shared__ double sd[NTHR];

  const int bid = blockIdx.x;
  const int tid = threadIdx.x;
  const int gid4 = (bid * NTHR + tid) * 4;

  for (int step = 0; step < MAX_STEPS; ++step) {
    // phase P: apply previous step's update + compute this step's h (block 0)
    update_phase(gid4, out);
    if (bid == 0 && tid == 0) {
      int si = g_si;
      int done = (si >= TT) ? 1 : 0;
      int sic = si < (TT - 1) ? si : (TT - 1);
      float tns = __ldg(ts + sic);
      float h = done ? 0.f : fmaxf(fminf(g_dt, tns - g_t), 0.f);
      g_done = done; g_sic = sic; g_tns = tns; g_h = h;
    }
    gsync();

    do_stage<0>(bid, W0, b0, W1, b1, W2, b2, As, Bs, sd);
    do_stage<1>(bid, W0, b0, W1, b1, W2, b2, As, Bs, sd);
    do_stage<2>(bid, W0, b0, W1, b1, W2, b2, As, Bs, sd);
    do_stage<3>(bid, W0, b0, W1, b1, W2, b2, As, Bs, sd);
    do_stage<4>(bid, W0, b0, W1, b1, W2, b2, As, Bs, sd);
    do_stage<5>(bid, W0, b0, W1, b1, W2, b2, As, Bs, sd);
    do_stage<6>(bid, W0, b0, W1, b1, W2, b2, As, Bs, sd);

    // control post (block 0 reduces error partials, updates controller state)
    if (bid == 0) {
      double v = (tid < NBLK) ? ((volatile double*)g_errpart)[tid] : 0.0;
      sd[tid] = v;
      __syncthreads();
      #pragma unroll
      for (int s2 = 128; s2 > 0; s2 >>= 1) {
        if (tid < s2) sd[tid] += sd[tid + s2];
        __syncthreads();
      }
      if (tid == 0) {
        float enorm = sqrtf((float)(sd[0] / (double)NELEM));
        int done = g_done;
        float h = g_h;
        int accept = (enorm <= 1.0f) && !done;
        float t_new = g_t + h;
        int hit = accept && (t_new >= g_tns - 1e-6f);
        if (accept) g_t = t_new;
        g_accept = accept;
        g_hit = hit;
        g_wrow = g_sic;
        g_si = g_si + hit;
        float factor;
        if (enorm > 0.f) {
          factor = 0.9f * powf(enorm, -0.2f);
          factor = fminf(fmaxf(factor, 0.2f), 10.f);
        } else {
          factor = 10.f;
        }
        if (!done) g_dt = g_dt * factor;
      }
    }
    gsync();
  }
  // final update for the last step
  update_phase(gid4, out);
}

__global__ void init_kernel(const float* __restrict__ ts,
                            const float* __restrict__ y0,
                            float* __restrict__ out) {
  int idx = blockIdx.x * NTHR + threadIdx.x;   // grid covers TT*NELEM
  if (idx < NELEM) {
    float v = y0[idx];
    out[idx] = v;
    g_y[idx] = v;
  } else {
    out[idx] = 0.f;
  }
  if (idx == 0) {
    g_t = ts[0];
    g_dt = ts[1] - ts[0];
    g_si = 1;
    g_accept = 0;
    g_hit = 0;
    g_wrow = 0;
    g_arrive = 0u;
  }
}

extern "C" void kernel_launch(void* const* d_in, const int* in_sizes, int n_in,
                              void* d_out, int out_size) {
  const float* ts = (const float*)d_in[0];
  const float* y0 = (const float*)d_in[1];
  const float* W0 = (const float*)d_in[2];
  const float* b0 = (const float*)d_in[3];
  const float* W1 = (const float*)d_in[4];
  const float* b1 = (const float*)d_in[5];
  const float* W2 = (const float*)d_in[6];
  const float* b2 = (const float*)d_in[7];
  float* out = (float*)d_out;

  init_kernel<<<(TT * NELEM) / NTHR, NTHR>>>(ts, y0, out);
  solve_kernel<<<NBLK, NTHR>>>(ts, W0, b0, W1, b1, W2, b2, out);
}

// round 5
// speedup vs baseline: 1.6205x; 1.6205x over previous
#include <cuda_runtime.h>
#include <cuda_bf16.h>
#include <math.h>
#include <stdint.h>

typedef __nv_bfloat16 bf16;

#define BB 1024
#define DD 128
#define WW 512
#define TT 8
#define NELEM (BB*DD)
#define HELEM (BB*WW)
#define MAX_STEPS 48
#define NBLK 128
#define NTHR 256
#define RTOLc 1e-3f
#define ATOLc 1e-6f
#define SAS 72   // SMEM row stride in bf16 (144B -> conflict-free frags)

#define A21f 0.161f
#define A31f (-0.008480655492356989f)
#define A32f 0.335480655492357f
#define A41f 2.8971530571054935f
#define A42f (-6.359448489975075f)
#define A43f 4.3622954328695815f
#define A51f 5.325864828439257f
#define A52f (-11.748883564062828f)
#define A53f 7.4955393428898365f
#define A54f (-0.09249506636175525f)
#define A61f 5.86145544294642f
#define A62f (-12.92096931784711f)
#define A63f 8.159367898576159f
#define A64f (-0.071584973281401f)
#define A65f (-0.028269050394068383f)
#define Bc1 0.09646076681806523f
#define Bc2 0.01f
#define Bc3 0.4798896504144996f
#define Bc4 1.379008574103742f
#define Bc5 (-3.290069515436081f)
#define Bc6 2.324710524099774f
#define Ec1 (-0.00178001105222577714f)
#define Ec2 (-0.0008164344596567469f)
#define Ec3 0.007880878010261995f
#define Ec4 (-0.1447110071732629f)
#define Ec5 0.5823571654525552f
#define Ec6 (-0.45808210592918697f)
#define Ec7 0.015151515151515152f

// ---------------- device state ----------------
__device__ __align__(16) float g_y[NELEM], g_ynew[NELEM], g_k[7][NELEM], g_part[4][NELEM];
__device__ __align__(16) bf16 g_Xhi[NELEM], g_Xlo[NELEM];
__device__ __align__(16) bf16 g_H1hi[HELEM], g_H1lo[HELEM];
__device__ __align__(16) bf16 g_H2hi[HELEM], g_H2lo[HELEM];
__device__ __align__(16) bf16 g_W0hi[WW*DD], g_W0lo[WW*DD];
__device__ __align__(16) bf16 g_W1hi[WW*WW], g_W1lo[WW*WW];
__device__ __align__(16) bf16 g_W2hi[DD*WW], g_W2lo[DD*WW];
__device__ double g_errpart[NBLK];
__device__ volatile float g_t, g_dt, g_h, g_tns;
__device__ volatile int g_si, g_sic, g_done, g_accept, g_hit, g_wrow;
__device__ unsigned g_arrive;

__constant__ float c_coef[6][6] = {
  {A21f,0,0,0,0,0},
  {A31f,A32f,0,0,0,0},
  {A41f,A42f,A43f,0,0,0},
  {A51f,A52f,A53f,A54f,0,0},
  {A61f,A62f,A63f,A64f,A65f,0},
  {Bc1,Bc2,Bc3,Bc4,Bc5,Bc6},
};

// -------- grid barrier --------
__device__ __forceinline__ void gsync() {
  __syncthreads();
  if (threadIdx.x == 0) {
    __threadfence();
    unsigned t = atomicAdd(&g_arrive, 1u) + 1u;
    unsigned target = ((t + NBLK - 1u) / NBLK) * NBLK;
    while (*(volatile unsigned*)&g_arrive < target) {}
    __threadfence();
  }
  __syncthreads();
}

// -------- MUFU-free softplus (abs err ~2e-6) --------
__device__ __forceinline__ float softplus_f(float x) {
  float t = fabsf(x);
  float s = fminf(t * 1.4426950408889634f, 100.f);
  float n = floorf(s);
  float r = n - s;                       // (-1, 0]
  // 2^r, r in (-1,0], deg-8 Taylor of exp(r*ln2)
  float p = 1.3215487e-6f;
  p = fmaf(p, r, 1.5252734e-5f);
  p = fmaf(p, r, 1.5403530e-4f);
  p = fmaf(p, r, 1.3333558e-3f);
  p = fmaf(p, r, 9.6181291e-3f);
  p = fmaf(p, r, 5.5504109e-2f);
  p = fmaf(p, r, 2.4022651e-1f);
  p = fmaf(p, r, 6.9314718e-1f);
  p = fmaf(p, r, 1.0f);
  float u = p * __uint_as_float((uint32_t)(127 - (int)n) << 23);  // exp(-t)
  // log1p(u) = 2*atanh(u/(2+u)); reciprocal via Newton (no MUFU)
  float d = 2.f + u;
  float w = fmaf(-0.1635f, u, 0.4915f);
  w = w * fmaf(-d, w, 2.f);
  w = w * fmaf(-d, w, 2.f);
  float v = u * w;
  float v2 = v * v;
  float g = 0.09090909f;
  g = fmaf(g, v2, 0.11111111f);
  g = fmaf(g, v2, 0.14285714f);
  g = fmaf(g, v2, 0.2f);
  g = fmaf(g, v2, 0.33333333f);
  g = fmaf(g, v2, 1.0f);
  return fmaxf(x, 0.f) + 2.f * v * g;
}

__device__ __forceinline__ void split_pack(float x0, float x1, uint32_t& hv, uint32_t& lv) {
  bf16 h0 = __float2bfloat16(x0), h1 = __float2bfloat16(x1);
  bf16 l0 = __float2bfloat16(x0 - __bfloat162float(h0));
  bf16 l1 = __float2bfloat16(x1 - __bfloat162float(h1));
  hv = (uint32_t)__bfloat16_as_ushort(h0) | ((uint32_t)__bfloat16_as_ushort(h1) << 16);
  lv = (uint32_t)__bfloat16_as_ushort(l0) | ((uint32_t)__bfloat16_as_ushort(l1) << 16);
}

__device__ __forceinline__ void mma16816(float* c, const uint32_t* a, const uint32_t* b) {
  asm volatile(
    "mma.sync.aligned.m16n8k16.row.col.f32.bf16.bf16.f32 "
    "{%0,%1,%2,%3}, {%4,%5,%6,%7}, {%8,%9}, {%0,%1,%2,%3};"
    : "+f"(c[0]), "+f"(c[1]), "+f"(c[2]), "+f"(c[3])
    : "r"(a[0]), "r"(a[1]), "r"(a[2]), "r"(a[3]), "r"(b[0]), "r"(b[1]));
}

// ---------------- HMMA GEMM: C[128,32] tile of A[M,K] @ B[N,K]^T ----------------
// 2-term bf16 split: C += Ahi*Bhi + Ahi*Blo + Alo*Bhi, fp32 accum.
// A (activations) read with __ldcg; B (weights) with __ldg.
template<bool SP, bool FOUT>
__device__ __forceinline__ void mma_gemm(
    const bf16* __restrict__ Ahi, const bf16* __restrict__ Alo,
    const bf16* __restrict__ Bhi, const bf16* __restrict__ Blo,
    int ldk, int bm, int bn, int kbase, int nchunk,
    const float* __restrict__ bias,
    bf16* __restrict__ Chi, bf16* __restrict__ Clo,
    float* __restrict__ Cf, int ldc,
    bf16* sAhi, bf16* sAlo, bf16* sBhi, bf16* sBlo)
{
  const int tid = threadIdx.x;
  const int wid = tid >> 5;
  const int lane = tid & 31;
  const int grp = lane >> 2;       // 0..7
  const int tig = lane & 3;        // 0..3
  const int wm = wid >> 1;         // 0..3 -> m offset 32*wm
  const int wn = wid & 1;          // 0..1 -> n offset 16*wn

  float acc[2][2][4] = {};

  // fill index precompute: A = 1024 uint4 per buf (4/thread), B = 256 per buf (1/thread)
  int ar[4], as[4];
  #pragma unroll
  for (int i = 0; i < 4; ++i) {
    int lin = tid + i * 256;
    ar[i] = lin >> 3;          // row 0..127
    as[i] = (lin & 7) << 3;    // seg col 0,8,..56
  }
  const int br = tid >> 3;     // 0..31
  const int bs = (tid & 7) << 3;

  uint4 pah[4], pal[4], pbh, pbl;
  {
    int k0 = kbase;
    #pragma unroll
    for (int i = 0; i < 4; ++i) {
      pah[i] = __ldcg((const uint4*)(Ahi + (bm + ar[i]) * ldk + k0 + as[i]));
      pal[i] = __ldcg((const uint4*)(Alo + (bm + ar[i]) * ldk + k0 + as[i]));
    }
    pbh = __ldg((const uint4*)(Bhi + (bn + br) * ldk + k0 + bs));
    pbl = __ldg((const uint4*)(Blo + (bn + br) * ldk + k0 + bs));
  }

  for (int c = 0; c < nchunk; ++c) {
    #pragma unroll
    for (int i = 0; i < 4; ++i) {
      *(uint4*)(sAhi + ar[i] * SAS + as[i]) = pah[i];
      *(uint4*)(sAlo + ar[i] * SAS + as[i]) = pal[i];
    }
    *(uint4*)(sBhi + br * SAS + bs) = pbh;
    *(uint4*)(sBlo + br * SAS + bs) = pbl;
    if (c + 1 < nchunk) {
      int k0 = kbase + (c + 1) * 64;
      #pragma unroll
      for (int i = 0; i < 4; ++i) {
        pah[i] = __ldcg((const uint4*)(Ahi + (bm + ar[i]) * ldk + k0 + as[i]));
        pal[i] = __ldcg((const uint4*)(Alo + (bm + ar[i]) * ldk + k0 + as[i]));
      }
      pbh = __ldg((const uint4*)(Bhi + (bn + br) * ldk + k0 + bs));
      pbl = __ldg((const uint4*)(Blo + (bn + br) * ldk + k0 + bs));
    }
    __syncthreads();
    #pragma unroll
    for (int ks = 0; ks < 4; ++ks) {
      const int kc = ks * 16;
      uint32_t ah[2][4], al[2][4], bh[2][2], bl[2][2];
      #pragma unroll
      for (int mi = 0; mi < 2; ++mi) {
        int r0 = wm * 32 + mi * 16 + grp;
        int c0 = kc + tig * 2;
        ah[mi][0] = *(const uint32_t*)(sAhi + r0 * SAS + c0);
        ah[mi][1] = *(const uint32_t*)(sAhi + (r0 + 8) * SAS + c0);
        ah[mi][2] = *(const uint32_t*)(sAhi + r0 * SAS + c0 + 8);
        ah[mi][3] = *(const uint32_t*)(sAhi + (r0 + 8) * SAS + c0 + 8);
        al[mi][0] = *(const uint32_t*)(sAlo + r0 * SAS + c0);
        al[mi][1] = *(const uint32_t*)(sAlo + (r0 + 8) * SAS + c0);
        al[mi][2] = *(const uint32_t*)(sAlo + r0 * SAS + c0 + 8);
        al[mi][3] = *(const uint32_t*)(sAlo + (r0 + 8) * SAS + c0 + 8);
      }
      #pragma unroll
      for (int ni = 0; ni < 2; ++ni) {
        int nr = wn * 16 + ni * 8 + grp;
        int c0 = kc + tig * 2;
        bh[ni][0] = *(const uint32_t*)(sBhi + nr * SAS + c0);
        bh[ni][1] = *(const uint32_t*)(sBhi + nr * SAS + c0 + 8);
        bl[ni][0] = *(const uint32_t*)(sBlo + nr * SAS + c0);
        bl[ni][1] = *(const uint32_t*)(sBlo + nr * SAS + c0 + 8);
      }
      #pragma unroll
      for (int mi = 0; mi < 2; ++mi)
        #pragma unroll
        for (int ni = 0; ni < 2; ++ni) {
          mma16816(acc[mi][ni], ah[mi], bh[ni]);
          mma16816(acc[mi][ni], ah[mi], bl[ni]);
          mma16816(acc[mi][ni], al[mi], bh[ni]);
        }
    }
    __syncthreads();
  }

  // epilogue
  #pragma unroll
  for (int mi = 0; mi < 2; ++mi) {
    #pragma unroll
    for (int ni = 0; ni < 2; ++ni) {
      int m0 = bm + wm * 32 + mi * 16 + grp;
      int n  = bn + wn * 16 + ni * 8 + tig * 2;
      float c0 = acc[mi][ni][0], c1 = acc[mi][ni][1];
      float c2 = acc[mi][ni][2], c3 = acc[mi][ni][3];
      if constexpr (FOUT) {
        float2 v0 = {c0, c1}, v1 = {c2, c3};
        __stcg((float2*)(Cf + m0 * ldc + n), v0);
        __stcg((float2*)(Cf + (m0 + 8) * ldc + n), v1);
      } else {
        float bv0 = __ldg(bias + n), bv1 = __ldg(bias + n + 1);
        float x0 = c0 + bv0, x1 = c1 + bv1;
        float x2 = c2 + bv0, x3 = c3 + bv1;
        if constexpr (SP) {
          x0 = softplus_f(x0); x1 = softplus_f(x1);
          x2 = softplus_f(x2); x3 = softplus_f(x3);
        }
        uint32_t hv, lv;
        split_pack(x0, x1, hv, lv);
        __stcg((uint32_t*)(Chi + m0 * ldc + n), hv);
        __stcg((uint32_t*)(Clo + m0 * ldc + n), lv);
        split_pack(x2, x3, hv, lv);
        __stcg((uint32_t*)(Chi + (m0 + 8) * ldc + n), hv);
        __stcg((uint32_t*)(Clo + (m0 + 8) * ldc + n), lv);
      }
    }
  }
}

// ---------- split-K reduce + fused epilogues + next-X build ----------
template<int S>
__device__ __forceinline__ void reduce_phase(int bid, int tid,
                                             const float* __restrict__ b2, double* sd)
{
  const int idx = (bid * NTHR + tid) * 4;
  float4 p0 = __ldcg((const float4*)(g_part[0] + idx));
  float4 p1 = __ldcg((const float4*)(g_part[1] + idx));
  float4 p2 = __ldcg((const float4*)(g_part[2] + idx));
  float4 p3 = __ldcg((const float4*)(g_part[3] + idx));
  const float* bp = b2 + (idx & (DD - 1));
  float4 v;
  v.x = p0.x + p1.x + p2.x + p3.x + __ldg(bp + 0);
  v.y = p0.y + p1.y + p2.y + p3.y + __ldg(bp + 1);
  v.z = p0.z + p1.z + p2.z + p3.z + __ldg(bp + 2);
  v.w = p0.w + p1.w + p2.w + p3.w + __ldg(bp + 3);
  __stcg((float4*)(g_k[S] + idx), v);
  float h = g_h;

  if constexpr (S <= 5) {
    float4 y4 = __ldcg((const float4*)(g_y + idx));
    float cS = c_coef[S][S];
    float4 acc;
    acc.x = cS * v.x; acc.y = cS * v.y; acc.z = cS * v.z; acc.w = cS * v.w;
    #pragma unroll
    for (int j = 0; j < S; ++j) {
      float cj = c_coef[S][j];
      float4 kj = __ldcg((const float4*)(g_k[j] + idx));
      acc.x = fmaf(cj, kj.x, acc.x); acc.y = fmaf(cj, kj.y, acc.y);
      acc.z = fmaf(cj, kj.z, acc.z); acc.w = fmaf(cj, kj.w, acc.w);
    }
    float4 X;
    X.x = fmaf(h, acc.x, y4.x); X.y = fmaf(h, acc.y, y4.y);
    X.z = fmaf(h, acc.z, y4.z); X.w = fmaf(h, acc.w, y4.w);
    if constexpr (S == 5) __stcg((float4*)(g_ynew + idx), X);
    uint2 hv, lv;
    split_pack(X.x, X.y, hv.x, lv.x);
    split_pack(X.z, X.w, hv.y, lv.y);
    __stcg((uint2*)(g_Xhi + idx), hv);
    __stcg((uint2*)(g_Xlo + idx), lv);
  } else {
    float4 k0 = __ldcg((const float4*)(g_k[0] + idx));
    float4 k1 = __ldcg((const float4*)(g_k[1] + idx));
    float4 k2 = __ldcg((const float4*)(g_k[2] + idx));
    float4 k3 = __ldcg((const float4*)(g_k[3] + idx));
    float4 k4 = __ldcg((const float4*)(g_k[4] + idx));
    float4 k5 = __ldcg((const float4*)(g_k[5] + idx));
    float4 y4 = __ldcg((const float4*)(g_y + idx));
    float4 yn = __ldcg((const float4*)(g_ynew + idx));
    double ss = 0.0;
    #pragma unroll
    for (int c = 0; c < 4; ++c) {
      float e = Ec1 * (&k0.x)[c];
      e = fmaf(Ec2, (&k1.x)[c], e);
      e = fmaf(Ec3, (&k2.x)[c], e);
      e = fmaf(Ec4, (&k3.x)[c], e);
      e = fmaf(Ec5, (&k4.x)[c], e);
      e = fmaf(Ec6, (&k5.x)[c], e);
      e = fmaf(Ec7, (&v.x)[c], e);
      float err = h * e;
      float scale = ATOLc + RTOLc * fmaxf(fabsf((&y4.x)[c]), fabsf((&yn.x)[c]));
      float r = err / scale;
      ss += (double)r * (double)r;
    }
    sd[tid] = ss;
    __syncthreads();
    #pragma unroll
    for (int s2 = 128; s2 > 0; s2 >>= 1) {
      if (tid < s2) sd[tid] += sd[tid + s2];
      __syncthreads();
    }
    if (tid == 0) ((volatile double*)g_errpart)[bid] = sd[0];
  }
}

template<int S>
__device__ __forceinline__ void do_stage(
    int bid, const float* b0, const float* b1, const float* b2,
    bf16* sAhi, bf16* sAlo, bf16* sBhi, bf16* sBlo, double* sd)
{
  int bm = (bid >> 4) << 7, bn = (bid & 15) << 5;
  mma_gemm<true, false>(g_Xhi, g_Xlo, g_W0hi, g_W0lo, DD, bm, bn, 0, 2, b0,
                        g_H1hi, g_H1lo, nullptr, WW, sAhi, sAlo, sBhi, sBlo);
  gsync();
  mma_gemm<true, false>(g_H1hi, g_H1lo, g_W1hi, g_W1lo, WW, bm, bn, 0, 8, b1,
                        g_H2hi, g_H2lo, nullptr, WW, sAhi, sAlo, sBhi, sBlo);
  gsync();
  int sl = bid & 3, t2 = bid >> 2;
  int bm3 = (t2 >> 2) << 7, bn3 = (t2 & 3) << 5;
  mma_gemm<false, true>(g_H2hi, g_H2lo, g_W2hi, g_W2lo, WW, bm3, bn3, sl * 128, 2, nullptr,
                        nullptr, nullptr, g_part[sl], DD, sAhi, sAlo, sBhi, sBlo);
  gsync();
  reduce_phase<S>(bid, threadIdx.x, b2, sd);
  gsync();
}

__device__ __forceinline__ void update_phase(int gid4, float* __restrict__ out) {
  float4 v;
  if (g_accept) {
    v = __ldcg((const float4*)(g_ynew + gid4));
    __stcg((float4*)(g_y + gid4), v);
    if (g_hit) *(float4*)(out + g_wrow * NELEM + gid4) = v;
  } else {
    v = __ldcg((const float4*)(g_y + gid4));
  }
  uint2 hv, lv;
  split_pack(v.x, v.y, hv.x, lv.x);
  split_pack(v.z, v.w, hv.y, lv.y);
  __stcg((uint2*)(g_Xhi + gid4), hv);
  __stcg((uint2*)(g_Xlo + gid4), lv);
}

// ---------------- persistent solver ----------------
__global__ void __launch_bounds__(NTHR, 1) solve_kernel(
    const float* __restrict__ ts,
    const float* __restrict__ b0, const float* __restrict__ b1,
    const float* __restrict__ b2, float* __restrict__ out)
{
  __shared__ __align__(16) bf16 sAhi[128 * SAS];
  __shared__ __align__(16) bf16 sAlo[128 * SAS];
  __shared__ __align__(16) bf16 sBhi[32 * SAS];
  __shared__ __align__(16) bf16 sBlo[32 * SAS];
  __shared__ double sd[NTHR];

  const int bid = blockIdx.x;
  const int tid = threadIdx.x;
  const int gid4 = (bid * NTHR + tid) * 4;

  for (int step = 0; step < MAX_STEPS; ++step) {
    update_phase(gid4, out);
    if (bid == 0 && tid == 0) {
      int si = g_si;
      int done = (si >= TT) ? 1 : 0;
      int sic = si < (TT - 1) ? si : (TT - 1);
      float tns = __ldg(ts + sic);
      float h = done ? 0.f : fmaxf(fminf(g_dt, tns - g_t), 0.f);
      g_done = done; g_sic = sic; g_tns = tns; g_h = h;
    }
    gsync();

    do_stage<0>(bid, b0, b1, b2, sAhi, sAlo, sBhi, sBlo, sd);
    do_stage<1>(bid, b0, b1, b2, sAhi, sAlo, sBhi, sBlo, sd);
    do_stage<2>(bid, b0, b1, b2, sAhi, sAlo, sBhi, sBlo, sd);
    do_stage<3>(bid, b0, b1, b2, sAhi, sAlo, sBhi, sBlo, sd);
    do_stage<4>(bid, b0, b1, b2, sAhi, sAlo, sBhi, sBlo, sd);
    do_stage<5>(bid, b0, b1, b2, sAhi, sAlo, sBhi, sBlo, sd);
    do_stage<6>(bid, b0, b1, b2, sAhi, sAlo, sBhi, sBlo, sd);

    if (bid == 0) {
      double v = (tid < NBLK) ? ((volatile double*)g_errpart)[tid] : 0.0;
      sd[tid] = v;
      __syncthreads();
      #pragma unroll
      for (int s2 = 128; s2 > 0; s2 >>= 1) {
        if (tid < s2) sd[tid] += sd[tid + s2];
        __syncthreads();
      }
      if (tid == 0) {
        float enorm = sqrtf((float)(sd[0] / (double)NELEM));
        int done = g_done;
        float h = g_h;
        int accept = (enorm <= 1.0f) && !done;
        float t_new = g_t + h;
        int hit = accept && (t_new >= g_tns - 1e-6f);
        if (accept) g_t = t_new;
        g_accept = accept;
        g_hit = hit;
        g_wrow = g_sic;
        g_si = g_si + hit;
        float factor;
        if (enorm > 0.f) {
          factor = 0.9f * powf(enorm, -0.2f);
          factor = fminf(fmaxf(factor, 0.2f), 10.f);
        } else factor = 10.f;
        if (!done) g_dt = g_dt * factor;
      }
    }
    gsync();
  }
  update_phase(gid4, out);
}

// ---------------- init: weights split, y0 split, out init ----------------
__global__ void init_kernel(const float* __restrict__ ts, const float* __restrict__ y0,
                            const float* __restrict__ W0, const float* __restrict__ W1,
                            const float* __restrict__ W2, float* __restrict__ out)
{
  int idx = blockIdx.x * NTHR + threadIdx.x;   // 4096*256 = TT*NELEM
  if (idx < TT * NELEM) out[idx] = (idx < NELEM) ? y0[idx] : 0.f;
  if (idx < NELEM) {
    float v = y0[idx];
    g_y[idx] = v;
    bf16 h = __float2bfloat16(v);
    g_Xhi[idx] = h;
    g_Xlo[idx] = __float2bfloat16(v - __bfloat162float(h));
  }
  if (idx < WW * DD) {
    float w = W0[idx];
    bf16 h = __float2bfloat16(w);
    g_W0hi[idx] = h; g_W0lo[idx] = __float2bfloat16(w - __bfloat162float(h));
    float w2 = W2[idx];
    bf16 h2 = __float2bfloat16(w2);
    g_W2hi[idx] = h2; g_W2lo[idx] = __float2bfloat16(w2 - __bfloat162float(h2));
  }
  if (idx < WW * WW) {
    float w = W1[idx];
    bf16 h = __float2bfloat16(w);
    g_W1hi[idx] = h; g_W1lo[idx] = __float2bfloat16(w - __bfloat162float(h));
  }
  if (idx == 0) {
    g_t = ts[0];
    g_dt = ts[1] - ts[0];
    g_si = 1;
    g_accept = 0;
    g_hit = 0;
    g_wrow = 0;
    g_arrive = 0u;
  }
}

extern "C" void kernel_launch(void* const* d_in, const int* in_sizes, int n_in,
                              void* d_out, int out_size) {
  const float* ts = (const float*)d_in[0];
  const float* y0 = (const float*)d_in[1];
  const float* W0 = (const float*)d_in[2];
  const float* b0 = (const float*)d_in[3];
  const float* W1 = (const float*)d_in[4];
  const float* b1 = (const float*)d_in[5];
  const float* W2 = (const float*)d_in[6];
  const float* b2 = (const float*)d_in[7];
  float* out = (float*)d_out;

  init_kernel<<<(TT * NELEM) / NTHR, NTHR>>>(ts, y0, W0, W1, W2, out);
  solve_kernel<<<NBLK, NTHR>>>(ts, b0, b1, b2, out);
}